// round 1
// baseline (speedup 1.0000x reference)
#include <cuda_runtime.h>
#include <math.h>

#define BB 4
#define NN 8192
#define HH 256

// ---------------- device scratch (no allocations allowed) ----------------
__device__ float g_tproj[BB*HH];
__device__ float g_pbest[4*BB*NN];
__device__ int   g_pidx [4*BB*NN];
__device__ float g_nearest[BB*NN*3];

// =====================================================================
// Kernel 1: time embedding  (B=4 blocks x 512 threads)
// =====================================================================
__global__ void temb_kernel(const int* __restrict__ timesteps,
                            const float* __restrict__ te_w1, const float* __restrict__ te_b1,
                            const float* __restrict__ te_w2, const float* __restrict__ te_b2,
                            const float* __restrict__ tp_w,  const float* __restrict__ tp_b)
{
    __shared__ float emb[128];
    __shared__ float h1[512];
    __shared__ float h2[512];
    int b = blockIdx.x, t = threadIdx.x;
    if (t < 64) {
        float freq = expf((float)t * (-logf(10000.0f) / 63.0f));
        float ang  = (float)timesteps[b] * freq;
        emb[t]      = sinf(ang);
        emb[t + 64] = cosf(ang);
    }
    __syncthreads();
    {
        float a = te_b1[t];
        #pragma unroll 4
        for (int k = 0; k < 128; k++) a = fmaf(emb[k], te_w1[k*512 + t], a);
        h1[t] = a / (1.0f + expf(-a));           // silu
    }
    __syncthreads();
    {
        float a = te_b2[t];
        #pragma unroll 4
        for (int k = 0; k < 512; k++) a = fmaf(h1[k], te_w2[k*512 + t], a);
        h2[t] = a;
    }
    __syncthreads();
    if (t < 256) {
        float a = tp_b[t];
        #pragma unroll 4
        for (int k = 0; k < 512; k++) a = fmaf(h2[k], tp_w[k*256 + t], a);
        g_tproj[b*256 + t] = a;
    }
}

// =====================================================================
// Kernel 2: nearest-neighbor partial argmin
// grid = B * 64 point-chunks * 4 target-slices = 1024 blocks, 128 threads
// key e = 0.5*|t|^2 - p.t  (monotone transform of d^2 per point)
// =====================================================================
#define TS 2048
__global__ void nn_kernel(const float* __restrict__ noisy,
                          const float* __restrict__ target)
{
    __shared__ float4 ts[TS];
    int b     =  blockIdx.x >> 8;
    int chunk = (blockIdx.x >> 2) & 63;
    int slice =  blockIdx.x & 3;
    int t = threadIdx.x;

    const float4* tg4 = (const float4*)(target + ((size_t)b*NN + (size_t)slice*TS) * 3);
    for (int p4 = t; p4 < TS/4; p4 += 128) {
        float4 v0 = tg4[3*p4], v1 = tg4[3*p4+1], v2 = tg4[3*p4+2];
        ts[4*p4+0] = make_float4(v0.x, v0.y, v0.z, 0.5f*(v0.x*v0.x + v0.y*v0.y + v0.z*v0.z));
        ts[4*p4+1] = make_float4(v0.w, v1.x, v1.y, 0.5f*(v0.w*v0.w + v1.x*v1.x + v1.y*v1.y));
        ts[4*p4+2] = make_float4(v1.z, v1.w, v2.x, 0.5f*(v1.z*v1.z + v1.w*v1.w + v2.x*v2.x));
        ts[4*p4+3] = make_float4(v2.y, v2.z, v2.w, 0.5f*(v2.y*v2.y + v2.z*v2.z + v2.w*v2.w));
    }
    __syncthreads();

    int p = chunk*128 + t;
    const float* q = noisy + ((size_t)b*NN + p) * 3;
    float qx = -q[0], qy = -q[1], qz = -q[2];
    float best = INFINITY; int bidx = 0;
    #pragma unroll 8
    for (int j = 0; j < TS; j++) {
        float4 v = ts[j];
        float e = fmaf(qx, v.x, v.w);
        e = fmaf(qy, v.y, e);
        e = fmaf(qz, v.z, e);
        if (e < best) { best = e; bidx = j; }
    }
    int pi = b*NN + p;
    g_pbest[slice*(BB*NN) + pi] = best;
    g_pidx [slice*(BB*NN) + pi] = slice*TS + bidx;
}

// merge the 4 slices (ascending => first-min semantics) and gather coords
__global__ void nn_reduce_kernel(const float* __restrict__ target)
{
    int pi = blockIdx.x * 256 + threadIdx.x;        // 0..32767
    float best = g_pbest[pi]; int bidx = g_pidx[pi];
    #pragma unroll
    for (int s = 1; s < 4; s++) {
        float v = g_pbest[s*(BB*NN) + pi];
        if (v < best) { best = v; bidx = g_pidx[s*(BB*NN) + pi]; }
    }
    int b = pi >> 13;
    const float* tc = target + ((size_t)b*NN + bidx) * 3;
    g_nearest[pi*3+0] = tc[0];
    g_nearest[pi*3+1] = tc[1];
    g_nearest[pi*3+2] = tc[2];
}

// =====================================================================
// Kernel 3: fused pointwise residual MLP + head
// 512 blocks x 512 threads, 64 rows/block.  x kept in shared.
// thread tile: 4 rows (warp owns 4 full rows) x TC cols.
// =====================================================================
template<int TC>  // cols per thread; NC = 32*TC
__device__ __forceinline__ void gemm_add(const float* __restrict__ As,   // [64][256] smem
                                         const float* __restrict__ Wg,   // [256][NC] gmem
                                         float* ws,                       // [16][NC] smem staging
                                         float acc[4][TC], int t)
{
    constexpr int NC = 32*TC;
    int lane = t & 31, warp = t >> 5;
    int r0 = warp*4, c0 = lane*TC;
    #pragma unroll 1
    for (int kt = 0; kt < 16; kt++) {
        const float4* src = (const float4*)(Wg + kt*16*NC);
        float4* dst = (float4*)ws;
        constexpr int LD4 = 16*NC/4;
        #pragma unroll
        for (int i = t; i < LD4; i += 512) dst[i] = src[i];
        __syncthreads();
        #pragma unroll
        for (int kk = 0; kk < 16; kk += 4) {
            float4 a[4];
            #pragma unroll
            for (int i = 0; i < 4; i++)
                a[i] = *(const float4*)(As + (r0+i)*256 + kt*16 + kk);
            #pragma unroll
            for (int u = 0; u < 4; u++) {
                float bv[TC];
                #pragma unroll
                for (int j = 0; j < TC; j += 4) {
                    float4 bb = *(const float4*)(ws + (kk+u)*NC + c0 + j);
                    bv[j] = bb.x; bv[j+1] = bb.y; bv[j+2] = bb.z; bv[j+3] = bb.w;
                }
                #pragma unroll
                for (int i = 0; i < 4; i++) {
                    float av = (u==0) ? a[i].x : (u==1) ? a[i].y : (u==2) ? a[i].z : a[i].w;
                    #pragma unroll
                    for (int j = 0; j < TC; j++) acc[i][j] = fmaf(av, bv[j], acc[i][j]);
                }
            }
        }
        __syncthreads();
    }
}

__global__ __launch_bounds__(512, 1)
void mlp_kernel(const float* __restrict__ noisy,
                const float* __restrict__ in_w,  const float* __restrict__ in_b,
                const float* __restrict__ ly_w1, const float* __restrict__ ly_b1,
                const float* __restrict__ ly_g,  const float* __restrict__ ly_be,
                const float* __restrict__ ly_w2, const float* __restrict__ ly_b2,
                const float* __restrict__ out_w1, const float* __restrict__ out_b1,
                const float* __restrict__ out_w2, const float* __restrict__ out_b2,
                float* __restrict__ out)
{
    extern __shared__ float smem[];
    float* xs = smem;                // 64*256
    float* hs = smem + 64*256;       // 64*256
    float* ws = smem + 2*64*256;     // 16*256

    int t = threadIdx.x, lane = t & 31, warp = t >> 5;
    int b    = blockIdx.x >> 7;
    int row0 = (blockIdx.x & 127) * 64;
    int r0 = warp*4, c0 = lane*8;

    // ---------- build x = feat @ in_w + in_b + tproj[b] ----------
    {
        float f[4][6];
        #pragma unroll
        for (int i = 0; i < 4; i++) {
            int gp = (b*NN + row0 + r0 + i);
            f[i][0] = noisy[gp*3+0]; f[i][1] = noisy[gp*3+1]; f[i][2] = noisy[gp*3+2];
            f[i][3] = g_nearest[gp*3+0]; f[i][4] = g_nearest[gp*3+1]; f[i][5] = g_nearest[gp*3+2];
        }
        float acc[4][8];
        #pragma unroll
        for (int j = 0; j < 8; j++) {
            float base = in_b[c0+j] + g_tproj[b*256 + c0 + j];
            #pragma unroll
            for (int i = 0; i < 4; i++) acc[i][j] = base;
        }
        #pragma unroll
        for (int k = 0; k < 6; k++) {
            float4 w0 = *(const float4*)(in_w + k*256 + c0);
            float4 w1 = *(const float4*)(in_w + k*256 + c0 + 4);
            #pragma unroll
            for (int i = 0; i < 4; i++) {
                acc[i][0] = fmaf(f[i][k], w0.x, acc[i][0]);
                acc[i][1] = fmaf(f[i][k], w0.y, acc[i][1]);
                acc[i][2] = fmaf(f[i][k], w0.z, acc[i][2]);
                acc[i][3] = fmaf(f[i][k], w0.w, acc[i][3]);
                acc[i][4] = fmaf(f[i][k], w1.x, acc[i][4]);
                acc[i][5] = fmaf(f[i][k], w1.y, acc[i][5]);
                acc[i][6] = fmaf(f[i][k], w1.z, acc[i][6]);
                acc[i][7] = fmaf(f[i][k], w1.w, acc[i][7]);
            }
        }
        #pragma unroll
        for (int i = 0; i < 4; i++)
            #pragma unroll
            for (int j = 0; j < 8; j++) xs[(r0+i)*256 + c0 + j] = acc[i][j];
    }
    __syncthreads();

    // ---------- 4 residual layers ----------
    for (int l = 0; l < 4; l++) {
        float acc[4][8];
        // GEMM1: h = x @ W1 + b1
        {
            float4 b0 = *(const float4*)(ly_b1 + l*256 + c0);
            float4 b1 = *(const float4*)(ly_b1 + l*256 + c0 + 4);
            #pragma unroll
            for (int i = 0; i < 4; i++) {
                acc[i][0]=b0.x; acc[i][1]=b0.y; acc[i][2]=b0.z; acc[i][3]=b0.w;
                acc[i][4]=b1.x; acc[i][5]=b1.y; acc[i][6]=b1.z; acc[i][7]=b1.w;
            }
        }
        gemm_add<8>(xs, ly_w1 + l*65536, ws, acc, t);

        // LayerNorm + SiLU (each warp owns 4 full rows -> pure shuffle reduce)
        float gg[8], bbv[8];
        {
            float4 g0 = *(const float4*)(ly_g  + l*256 + c0);
            float4 g1 = *(const float4*)(ly_g  + l*256 + c0 + 4);
            float4 e0 = *(const float4*)(ly_be + l*256 + c0);
            float4 e1 = *(const float4*)(ly_be + l*256 + c0 + 4);
            gg[0]=g0.x; gg[1]=g0.y; gg[2]=g0.z; gg[3]=g0.w; gg[4]=g1.x; gg[5]=g1.y; gg[6]=g1.z; gg[7]=g1.w;
            bbv[0]=e0.x; bbv[1]=e0.y; bbv[2]=e0.z; bbv[3]=e0.w; bbv[4]=e1.x; bbv[5]=e1.y; bbv[6]=e1.z; bbv[7]=e1.w;
        }
        #pragma unroll
        for (int i = 0; i < 4; i++) {
            float s = 0.f;
            #pragma unroll
            for (int j = 0; j < 8; j++) s += acc[i][j];
            #pragma unroll
            for (int o = 16; o > 0; o >>= 1) s += __shfl_xor_sync(0xffffffffu, s, o);
            float mu = s * (1.0f/256.0f);
            float v = 0.f;
            #pragma unroll
            for (int j = 0; j < 8; j++) { float d = acc[i][j] - mu; v = fmaf(d, d, v); }
            #pragma unroll
            for (int o = 16; o > 0; o >>= 1) v += __shfl_xor_sync(0xffffffffu, v, o);
            float rs = rsqrtf(v * (1.0f/256.0f) + 1e-5f);
            #pragma unroll
            for (int j = 0; j < 8; j++) {
                float h  = (acc[i][j] - mu) * rs * gg[j] + bbv[j];
                hs[(r0+i)*256 + c0 + j] = h / (1.0f + expf(-h));  // silu
            }
        }
        __syncthreads();

        // GEMM2: x += silu(h) @ W2 + b2
        float acc2[4][8];
        {
            float4 b0 = *(const float4*)(ly_b2 + l*256 + c0);
            float4 b1 = *(const float4*)(ly_b2 + l*256 + c0 + 4);
            #pragma unroll
            for (int i = 0; i < 4; i++) {
                acc2[i][0]=b0.x; acc2[i][1]=b0.y; acc2[i][2]=b0.z; acc2[i][3]=b0.w;
                acc2[i][4]=b1.x; acc2[i][5]=b1.y; acc2[i][6]=b1.z; acc2[i][7]=b1.w;
            }
        }
        gemm_add<8>(hs, ly_w2 + l*65536, ws, acc2, t);
        #pragma unroll
        for (int i = 0; i < 4; i++)
            #pragma unroll
            for (int j = 0; j < 8; j++)
                xs[(r0+i)*256 + c0 + j] += acc2[i][j];   // residual (own element)
        __syncthreads();
    }

    // ---------- head: y1 = silu(x @ out_w1 + out_b1), N=128 ----------
    {
        int c1 = lane*4;
        float acc[4][4];
        float4 b0 = *(const float4*)(out_b1 + c1);
        #pragma unroll
        for (int i = 0; i < 4; i++) { acc[i][0]=b0.x; acc[i][1]=b0.y; acc[i][2]=b0.z; acc[i][3]=b0.w; }
        gemm_add<4>(xs, out_w1, ws, acc, t);
        #pragma unroll
        for (int i = 0; i < 4; i++)
            #pragma unroll
            for (int j = 0; j < 4; j++) {
                float v = acc[i][j];
                hs[(r0+i)*128 + c1 + j] = v / (1.0f + expf(-v));
            }
    }
    __syncthreads();

    // ---------- head: score = y1 @ out_w2 + out_b2 (128 -> 3) ----------
    if (t < 192) {
        int r = t / 3, p = t - r*3;
        float a = out_b2[p];
        const float* hr = hs + r*128;
        #pragma unroll 8
        for (int k = 0; k < 128; k++) a = fmaf(hr[k], out_w2[k*3 + p], a);
        out[((size_t)(b*NN + row0 + r))*3 + p] = a;
    }
}

// =====================================================================
extern "C" void kernel_launch(void* const* d_in, const int* in_sizes, int n_in,
                              void* d_out, int out_size)
{
    const float* noisy   = (const float*)d_in[0];
    const float* target  = (const float*)d_in[1];
    const int*   tsteps  = (const int*)  d_in[2];
    const float* te_w1   = (const float*)d_in[3];
    const float* te_b1   = (const float*)d_in[4];
    const float* te_w2   = (const float*)d_in[5];
    const float* te_b2   = (const float*)d_in[6];
    const float* tp_w    = (const float*)d_in[7];
    const float* tp_b    = (const float*)d_in[8];
    const float* in_w    = (const float*)d_in[9];
    const float* in_b    = (const float*)d_in[10];
    const float* ly_w1   = (const float*)d_in[11];
    const float* ly_b1   = (const float*)d_in[12];
    const float* ly_g    = (const float*)d_in[13];
    const float* ly_be   = (const float*)d_in[14];
    const float* ly_w2   = (const float*)d_in[15];
    const float* ly_b2   = (const float*)d_in[16];
    const float* out_w1  = (const float*)d_in[17];
    const float* out_b1  = (const float*)d_in[18];
    const float* out_w2  = (const float*)d_in[19];
    const float* out_b2  = (const float*)d_in[20];
    float* out = (float*)d_out;

    cudaFuncSetAttribute(mlp_kernel, cudaFuncAttributeMaxDynamicSharedMemorySize, 147456);

    temb_kernel<<<4, 512>>>(tsteps, te_w1, te_b1, te_w2, te_b2, tp_w, tp_b);
    nn_kernel<<<1024, 128>>>(noisy, target);
    nn_reduce_kernel<<<128, 256>>>(target);
    mlp_kernel<<<512, 512, 147456>>>(noisy, in_w, in_b,
                                     ly_w1, ly_b1, ly_g, ly_be, ly_w2, ly_b2,
                                     out_w1, out_b1, out_w2, out_b2, out);
}

// round 2
// speedup vs baseline: 1.0010x; 1.0010x over previous
#include <cuda_runtime.h>
#include <math.h>

#define BB 4
#define NN 8192
#define HH 256

// ---------------- device scratch (no allocations allowed) ----------------
__device__ float g_tproj[BB*HH];
__device__ float g_pbest[4*BB*NN];
__device__ int   g_pidx [4*BB*NN];
__device__ float g_nearest[BB*NN*3];

// =====================================================================
// Kernel 1: time embedding  (B=4 blocks x 512 threads)
// =====================================================================
__global__ void temb_kernel(const int* __restrict__ timesteps,
                            const float* __restrict__ te_w1, const float* __restrict__ te_b1,
                            const float* __restrict__ te_w2, const float* __restrict__ te_b2,
                            const float* __restrict__ tp_w,  const float* __restrict__ tp_b)
{
    __shared__ float emb[128];
    __shared__ float h1[512];
    __shared__ float h2[512];
    int b = blockIdx.x, t = threadIdx.x;
    if (t < 64) {
        float freq = expf((float)t * (-logf(10000.0f) / 63.0f));
        float ang  = (float)timesteps[b] * freq;
        emb[t]      = sinf(ang);
        emb[t + 64] = cosf(ang);
    }
    __syncthreads();
    {
        float a = te_b1[t];
        #pragma unroll 4
        for (int k = 0; k < 128; k++) a = fmaf(emb[k], te_w1[k*512 + t], a);
        h1[t] = a / (1.0f + expf(-a));           // silu
    }
    __syncthreads();
    {
        float a = te_b2[t];
        #pragma unroll 4
        for (int k = 0; k < 512; k++) a = fmaf(h1[k], te_w2[k*512 + t], a);
        h2[t] = a;
    }
    __syncthreads();
    if (t < 256) {
        float a = tp_b[t];
        #pragma unroll 4
        for (int k = 0; k < 512; k++) a = fmaf(h2[k], tp_w[k*256 + t], a);
        g_tproj[b*256 + t] = a;
    }
}

// =====================================================================
// Kernel 2: nearest-neighbor partial argmin
// grid = B * 64 point-chunks * 4 target-slices = 1024 blocks, 128 threads
// key e = 0.5*|t|^2 - p.t  (monotone transform of d^2 per point)
// =====================================================================
#define TS 2048
__global__ void nn_kernel(const float* __restrict__ noisy,
                          const float* __restrict__ target)
{
    __shared__ float4 ts[TS];
    int b     =  blockIdx.x >> 8;
    int chunk = (blockIdx.x >> 2) & 63;
    int slice =  blockIdx.x & 3;
    int t = threadIdx.x;

    const float4* tg4 = (const float4*)(target + ((size_t)b*NN + (size_t)slice*TS) * 3);
    for (int p4 = t; p4 < TS/4; p4 += 128) {
        float4 v0 = tg4[3*p4], v1 = tg4[3*p4+1], v2 = tg4[3*p4+2];
        ts[4*p4+0] = make_float4(v0.x, v0.y, v0.z, 0.5f*(v0.x*v0.x + v0.y*v0.y + v0.z*v0.z));
        ts[4*p4+1] = make_float4(v0.w, v1.x, v1.y, 0.5f*(v0.w*v0.w + v1.x*v1.x + v1.y*v1.y));
        ts[4*p4+2] = make_float4(v1.z, v1.w, v2.x, 0.5f*(v1.z*v1.z + v1.w*v1.w + v2.x*v2.x));
        ts[4*p4+3] = make_float4(v2.y, v2.z, v2.w, 0.5f*(v2.y*v2.y + v2.z*v2.z + v2.w*v2.w));
    }
    __syncthreads();

    int p = chunk*128 + t;
    const float* q = noisy + ((size_t)b*NN + p) * 3;
    float qx = -q[0], qy = -q[1], qz = -q[2];
    float best = INFINITY; int bidx = 0;
    #pragma unroll 8
    for (int j = 0; j < TS; j++) {
        float4 v = ts[j];
        float e = fmaf(qx, v.x, v.w);
        e = fmaf(qy, v.y, e);
        e = fmaf(qz, v.z, e);
        if (e < best) { best = e; bidx = j; }
    }
    int pi = b*NN + p;
    g_pbest[slice*(BB*NN) + pi] = best;
    g_pidx [slice*(BB*NN) + pi] = slice*TS + bidx;
}

// merge the 4 slices (ascending => first-min semantics) and gather coords
__global__ void nn_reduce_kernel(const float* __restrict__ target)
{
    int pi = blockIdx.x * 256 + threadIdx.x;        // 0..32767
    float best = g_pbest[pi]; int bidx = g_pidx[pi];
    #pragma unroll
    for (int s = 1; s < 4; s++) {
        float v = g_pbest[s*(BB*NN) + pi];
        if (v < best) { best = v; bidx = g_pidx[s*(BB*NN) + pi]; }
    }
    int b = pi >> 13;
    const float* tc = target + ((size_t)b*NN + bidx) * 3;
    g_nearest[pi*3+0] = tc[0];
    g_nearest[pi*3+1] = tc[1];
    g_nearest[pi*3+2] = tc[2];
}

// =====================================================================
// Kernel 3: fused pointwise residual MLP + head
// 512 blocks x 512 threads, 64 rows/block.  x kept in shared.
// thread tile: 4 rows (warp owns 4 full rows) x TC cols.
// =====================================================================
template<int TC>  // cols per thread; NC = 32*TC
__device__ __forceinline__ void gemm_add(const float* __restrict__ As,   // [64][256] smem
                                         const float* __restrict__ Wg,   // [256][NC] gmem
                                         float* ws,                       // [16][NC] smem staging
                                         float acc[4][TC], int t)
{
    constexpr int NC = 32*TC;
    int lane = t & 31, warp = t >> 5;
    int r0 = warp*4, c0 = lane*TC;
    #pragma unroll 1
    for (int kt = 0; kt < 16; kt++) {
        const float4* src = (const float4*)(Wg + kt*16*NC);
        float4* dst = (float4*)ws;
        constexpr int LD4 = 16*NC/4;
        #pragma unroll
        for (int i = t; i < LD4; i += 512) dst[i] = src[i];
        __syncthreads();
        #pragma unroll
        for (int kk = 0; kk < 16; kk += 4) {
            float4 a[4];
            #pragma unroll
            for (int i = 0; i < 4; i++)
                a[i] = *(const float4*)(As + (r0+i)*256 + kt*16 + kk);
            #pragma unroll
            for (int u = 0; u < 4; u++) {
                float bv[TC];
                #pragma unroll
                for (int j = 0; j < TC; j += 4) {
                    float4 bb = *(const float4*)(ws + (kk+u)*NC + c0 + j);
                    bv[j] = bb.x; bv[j+1] = bb.y; bv[j+2] = bb.z; bv[j+3] = bb.w;
                }
                #pragma unroll
                for (int i = 0; i < 4; i++) {
                    float av = (u==0) ? a[i].x : (u==1) ? a[i].y : (u==2) ? a[i].z : a[i].w;
                    #pragma unroll
                    for (int j = 0; j < TC; j++) acc[i][j] = fmaf(av, bv[j], acc[i][j]);
                }
            }
        }
        __syncthreads();
    }
}

__global__ __launch_bounds__(512, 1)
void mlp_kernel(const float* __restrict__ noisy,
                const float* __restrict__ in_w,  const float* __restrict__ in_b,
                const float* __restrict__ ly_w1, const float* __restrict__ ly_b1,
                const float* __restrict__ ly_g,  const float* __restrict__ ly_be,
                const float* __restrict__ ly_w2, const float* __restrict__ ly_b2,
                const float* __restrict__ out_w1, const float* __restrict__ out_b1,
                const float* __restrict__ out_w2, const float* __restrict__ out_b2,
                float* __restrict__ out)
{
    extern __shared__ float smem[];
    float* xs = smem;                // 64*256
    float* hs = smem + 64*256;       // 64*256
    float* ws = smem + 2*64*256;     // 16*256

    int t = threadIdx.x, lane = t & 31, warp = t >> 5;
    int b    = blockIdx.x >> 7;
    int row0 = (blockIdx.x & 127) * 64;
    int r0 = warp*4, c0 = lane*8;

    // ---------- build x = feat @ in_w + in_b + tproj[b] ----------
    {
        float f[4][6];
        #pragma unroll
        for (int i = 0; i < 4; i++) {
            int gp = (b*NN + row0 + r0 + i);
            f[i][0] = noisy[gp*3+0]; f[i][1] = noisy[gp*3+1]; f[i][2] = noisy[gp*3+2];
            f[i][3] = g_nearest[gp*3+0]; f[i][4] = g_nearest[gp*3+1]; f[i][5] = g_nearest[gp*3+2];
        }
        float acc[4][8];
        #pragma unroll
        for (int j = 0; j < 8; j++) {
            float base = in_b[c0+j] + g_tproj[b*256 + c0 + j];
            #pragma unroll
            for (int i = 0; i < 4; i++) acc[i][j] = base;
        }
        #pragma unroll
        for (int k = 0; k < 6; k++) {
            float4 w0 = *(const float4*)(in_w + k*256 + c0);
            float4 w1 = *(const float4*)(in_w + k*256 + c0 + 4);
            #pragma unroll
            for (int i = 0; i < 4; i++) {
                acc[i][0] = fmaf(f[i][k], w0.x, acc[i][0]);
                acc[i][1] = fmaf(f[i][k], w0.y, acc[i][1]);
                acc[i][2] = fmaf(f[i][k], w0.z, acc[i][2]);
                acc[i][3] = fmaf(f[i][k], w0.w, acc[i][3]);
                acc[i][4] = fmaf(f[i][k], w1.x, acc[i][4]);
                acc[i][5] = fmaf(f[i][k], w1.y, acc[i][5]);
                acc[i][6] = fmaf(f[i][k], w1.z, acc[i][6]);
                acc[i][7] = fmaf(f[i][k], w1.w, acc[i][7]);
            }
        }
        #pragma unroll
        for (int i = 0; i < 4; i++)
            #pragma unroll
            for (int j = 0; j < 8; j++) xs[(r0+i)*256 + c0 + j] = acc[i][j];
    }
    __syncthreads();

    // ---------- 4 residual layers ----------
    for (int l = 0; l < 4; l++) {
        float acc[4][8];
        // GEMM1: h = x @ W1 + b1
        {
            float4 b0 = *(const float4*)(ly_b1 + l*256 + c0);
            float4 b1 = *(const float4*)(ly_b1 + l*256 + c0 + 4);
            #pragma unroll
            for (int i = 0; i < 4; i++) {
                acc[i][0]=b0.x; acc[i][1]=b0.y; acc[i][2]=b0.z; acc[i][3]=b0.w;
                acc[i][4]=b1.x; acc[i][5]=b1.y; acc[i][6]=b1.z; acc[i][7]=b1.w;
            }
        }
        gemm_add<8>(xs, ly_w1 + l*65536, ws, acc, t);

        // LayerNorm + SiLU (each warp owns 4 full rows -> pure shuffle reduce)
        float gg[8], bbv[8];
        {
            float4 g0 = *(const float4*)(ly_g  + l*256 + c0);
            float4 g1 = *(const float4*)(ly_g  + l*256 + c0 + 4);
            float4 e0 = *(const float4*)(ly_be + l*256 + c0);
            float4 e1 = *(const float4*)(ly_be + l*256 + c0 + 4);
            gg[0]=g0.x; gg[1]=g0.y; gg[2]=g0.z; gg[3]=g0.w; gg[4]=g1.x; gg[5]=g1.y; gg[6]=g1.z; gg[7]=g1.w;
            bbv[0]=e0.x; bbv[1]=e0.y; bbv[2]=e0.z; bbv[3]=e0.w; bbv[4]=e1.x; bbv[5]=e1.y; bbv[6]=e1.z; bbv[7]=e1.w;
        }
        #pragma unroll
        for (int i = 0; i < 4; i++) {
            float s = 0.f;
            #pragma unroll
            for (int j = 0; j < 8; j++) s += acc[i][j];
            #pragma unroll
            for (int o = 16; o > 0; o >>= 1) s += __shfl_xor_sync(0xffffffffu, s, o);
            float mu = s * (1.0f/256.0f);
            float v = 0.f;
            #pragma unroll
            for (int j = 0; j < 8; j++) { float d = acc[i][j] - mu; v = fmaf(d, d, v); }
            #pragma unroll
            for (int o = 16; o > 0; o >>= 1) v += __shfl_xor_sync(0xffffffffu, v, o);
            float rs = rsqrtf(v * (1.0f/256.0f) + 1e-5f);
            #pragma unroll
            for (int j = 0; j < 8; j++) {
                float h  = (acc[i][j] - mu) * rs * gg[j] + bbv[j];
                hs[(r0+i)*256 + c0 + j] = h / (1.0f + expf(-h));  // silu
            }
        }
        __syncthreads();

        // GEMM2: x += silu(h) @ W2 + b2
        float acc2[4][8];
        {
            float4 b0 = *(const float4*)(ly_b2 + l*256 + c0);
            float4 b1 = *(const float4*)(ly_b2 + l*256 + c0 + 4);
            #pragma unroll
            for (int i = 0; i < 4; i++) {
                acc2[i][0]=b0.x; acc2[i][1]=b0.y; acc2[i][2]=b0.z; acc2[i][3]=b0.w;
                acc2[i][4]=b1.x; acc2[i][5]=b1.y; acc2[i][6]=b1.z; acc2[i][7]=b1.w;
            }
        }
        gemm_add<8>(hs, ly_w2 + l*65536, ws, acc2, t);
        #pragma unroll
        for (int i = 0; i < 4; i++)
            #pragma unroll
            for (int j = 0; j < 8; j++)
                xs[(r0+i)*256 + c0 + j] += acc2[i][j];   // residual (own element)
        __syncthreads();
    }

    // ---------- head: y1 = silu(x @ out_w1 + out_b1), N=128 ----------
    {
        int c1 = lane*4;
        float acc[4][4];
        float4 b0 = *(const float4*)(out_b1 + c1);
        #pragma unroll
        for (int i = 0; i < 4; i++) { acc[i][0]=b0.x; acc[i][1]=b0.y; acc[i][2]=b0.z; acc[i][3]=b0.w; }
        gemm_add<4>(xs, out_w1, ws, acc, t);
        #pragma unroll
        for (int i = 0; i < 4; i++)
            #pragma unroll
            for (int j = 0; j < 4; j++) {
                float v = acc[i][j];
                hs[(r0+i)*128 + c1 + j] = v / (1.0f + expf(-v));
            }
    }
    __syncthreads();

    // ---------- head: score = y1 @ out_w2 + out_b2 (128 -> 3) ----------
    if (t < 192) {
        int r = t / 3, p = t - r*3;
        float a = out_b2[p];
        const float* hr = hs + r*128;
        #pragma unroll 8
        for (int k = 0; k < 128; k++) a = fmaf(hr[k], out_w2[k*3 + p], a);
        out[((size_t)(b*NN + row0 + r))*3 + p] = a;
    }
}

// =====================================================================
extern "C" void kernel_launch(void* const* d_in, const int* in_sizes, int n_in,
                              void* d_out, int out_size)
{
    const float* noisy   = (const float*)d_in[0];
    const float* target  = (const float*)d_in[1];
    const int*   tsteps  = (const int*)  d_in[2];
    const float* te_w1   = (const float*)d_in[3];
    const float* te_b1   = (const float*)d_in[4];
    const float* te_w2   = (const float*)d_in[5];
    const float* te_b2   = (const float*)d_in[6];
    const float* tp_w    = (const float*)d_in[7];
    const float* tp_b    = (const float*)d_in[8];
    const float* in_w    = (const float*)d_in[9];
    const float* in_b    = (const float*)d_in[10];
    const float* ly_w1   = (const float*)d_in[11];
    const float* ly_b1   = (const float*)d_in[12];
    const float* ly_g    = (const float*)d_in[13];
    const float* ly_be   = (const float*)d_in[14];
    const float* ly_w2   = (const float*)d_in[15];
    const float* ly_b2   = (const float*)d_in[16];
    const float* out_w1  = (const float*)d_in[17];
    const float* out_b1  = (const float*)d_in[18];
    const float* out_w2  = (const float*)d_in[19];
    const float* out_b2  = (const float*)d_in[20];
    float* out = (float*)d_out;

    cudaFuncSetAttribute(mlp_kernel, cudaFuncAttributeMaxDynamicSharedMemorySize, 147456);

    temb_kernel<<<4, 512>>>(tsteps, te_w1, te_b1, te_w2, te_b2, tp_w, tp_b);
    nn_kernel<<<1024, 128>>>(noisy, target);
    nn_reduce_kernel<<<128, 256>>>(target);
    mlp_kernel<<<512, 512, 147456>>>(noisy, in_w, in_b,
                                     ly_w1, ly_b1, ly_g, ly_be, ly_w2, ly_b2,
                                     out_w1, out_b1, out_w2, out_b2, out);
}

// round 4
// speedup vs baseline: 2.6516x; 2.6490x over previous
#include <cuda_runtime.h>
#include <math.h>
#include <cstdint>

#define BB 4
#define NN 8192

// ---------------- device scratch ----------------
__device__ float g_tproj[BB*256];
__device__ float g_pbest[4*BB*NN];
__device__ int   g_pidx [4*BB*NN];
__device__ float g_nearest[BB*NN*3];
__device__ float g_wt1[4*256*256];   // ly_w1^T  [N][K], tf32-rounded
__device__ float g_wt2[4*256*256];   // ly_w2^T, tf32-rounded
__device__ float g_owt1[128*256];    // out_w1^T, tf32-rounded

// ================= helpers =================
__device__ __forceinline__ uint32_t smem_to_u32(const void* p) {
    uint32_t a;
    asm("{ .reg .u64 t; cvta.to.shared.u64 t, %1; cvt.u32.u64 %0, t; }" : "=r"(a) : "l"(p));
    return a;
}
__device__ __forceinline__ void cp_async16(uint32_t d, const void* s) {
    asm volatile("cp.async.ca.shared.global [%0], [%1], 16;" :: "r"(d), "l"(s) : "memory");
}
#define CP_COMMIT() asm volatile("cp.async.commit_group;" ::: "memory")
template<int N> __device__ __forceinline__ void cp_wait() {
    asm volatile("cp.async.wait_group %0;" :: "n"(N) : "memory");
}
__device__ __forceinline__ uint32_t tf32_bits(float f) {
    uint32_t u; asm("cvt.rna.tf32.f32 %0, %1;" : "=r"(u) : "f"(f)); return u;
}
__device__ __forceinline__ void mma8(float c[4], const uint32_t a[4], const uint32_t b[2]) {
    asm volatile(
        "mma.sync.aligned.m16n8k8.row.col.f32.tf32.tf32.f32 "
        "{%0,%1,%2,%3}, {%4,%5,%6,%7}, {%8,%9}, {%0,%1,%2,%3};"
        : "+f"(c[0]), "+f"(c[1]), "+f"(c[2]), "+f"(c[3])
        : "r"(a[0]), "r"(a[1]), "r"(a[2]), "r"(a[3]), "r"(b[0]), "r"(b[1]));
}
__device__ __forceinline__ float silu(float x) { return x / (1.0f + __expf(-x)); }

// swizzled index into a [64][256] tile (float granularity; 4-float unit XOR row&7)
__device__ __forceinline__ int xidx(int row, int col) {
    return row*256 + (((((col>>2) ^ (row & 7)) & 63) << 2) | (col & 3));
}

// smem float offsets
#define O_XS    0        // 16384 f
#define O_HS    16384    // 16384 f
#define O_WB    32768    // 18432 f (2 x 9216)
#define O_B1    51200
#define O_GA    51456
#define O_BE    51712
#define O_B2    51968
#define O_CV    52224
#define O_INW   52480    // 1536
#define O_OB1   54016    // 128
#define O_W2    54144    // 384
#define O_OB2   54528    // 4
#define O_SRS   54532    // 1024
#define O_SRQ   55556    // 1024
#define O_MU    56580    // 64
#define O_RS    56644    // 64
#define SMEM_F  56708
#define SMEM_BYTES (SMEM_F*4)

// ============ weight transpose + tf32 rounding ============
__global__ void transpose_kernel(const float* __restrict__ ly_w1,
                                 const float* __restrict__ ly_w2,
                                 const float* __restrict__ out_w1)
{
    __shared__ float ts[32][33];
    int m = blockIdx.x >> 6, tile = blockIdx.x & 63;
    const float* src; float* dst; int N = 256;
    if (m < 4)      { src = ly_w1 + m*65536;     dst = g_wt1 + m*65536; }
    else if (m < 8) { src = ly_w2 + (m-4)*65536; dst = g_wt2 + (m-4)*65536; }
    else            { src = out_w1;              dst = g_owt1; N = 128; }
    int tn = (tile & 7) * 32, tk = (tile >> 3) * 32;
    if (tn >= N) return;
    int lx = threadIdx.x & 31, ly = threadIdx.x >> 5;
    #pragma unroll
    for (int i = 0; i < 32; i += 8) ts[ly+i][lx] = src[(tk+ly+i)*N + tn + lx];
    __syncthreads();
    #pragma unroll
    for (int i = 0; i < 32; i += 8)
        dst[(tn+ly+i)*256 + tk + lx] = __uint_as_float(tf32_bits(ts[lx][ly+i]));
}

// ============ time embedding ============
__global__ void temb_kernel(const int* __restrict__ timesteps,
                            const float* __restrict__ te_w1, const float* __restrict__ te_b1,
                            const float* __restrict__ te_w2, const float* __restrict__ te_b2,
                            const float* __restrict__ tp_w,  const float* __restrict__ tp_b)
{
    __shared__ float emb[128], h1[512], h2[512];
    int b = blockIdx.x, t = threadIdx.x;
    if (t < 64) {
        float fr = expf((float)t * (-logf(10000.0f) / 63.0f));
        float an = (float)timesteps[b] * fr;
        emb[t] = sinf(an); emb[t+64] = cosf(an);
    }
    __syncthreads();
    { float a = te_b1[t];
      #pragma unroll 4
      for (int k = 0; k < 128; k++) a = fmaf(emb[k], te_w1[k*512+t], a);
      h1[t] = a / (1.0f + expf(-a)); }
    __syncthreads();
    { float a = te_b2[t];
      #pragma unroll 4
      for (int k = 0; k < 512; k++) a = fmaf(h1[k], te_w2[k*512+t], a);
      h2[t] = a; }
    __syncthreads();
    if (t < 256) {
        float a = tp_b[t];
        #pragma unroll 4
        for (int k = 0; k < 512; k++) a = fmaf(h2[k], tp_w[k*256+t], a);
        g_tproj[b*256+t] = a;
    }
}

// ============ nearest neighbor (known-good) ============
#define TSZ 2048
__global__ void nn_kernel(const float* __restrict__ noisy, const float* __restrict__ target)
{
    __shared__ float4 ts[TSZ];
    int b = blockIdx.x >> 8, chunk = (blockIdx.x >> 2) & 63, slice = blockIdx.x & 3;
    int t = threadIdx.x;
    const float4* tg4 = (const float4*)(target + ((size_t)b*NN + (size_t)slice*TSZ) * 3);
    for (int p4 = t; p4 < TSZ/4; p4 += 128) {
        float4 v0 = tg4[3*p4], v1 = tg4[3*p4+1], v2 = tg4[3*p4+2];
        ts[4*p4+0] = make_float4(v0.x, v0.y, v0.z, 0.5f*(v0.x*v0.x + v0.y*v0.y + v0.z*v0.z));
        ts[4*p4+1] = make_float4(v0.w, v1.x, v1.y, 0.5f*(v0.w*v0.w + v1.x*v1.x + v1.y*v1.y));
        ts[4*p4+2] = make_float4(v1.z, v1.w, v2.x, 0.5f*(v1.z*v1.z + v1.w*v1.w + v2.x*v2.x));
        ts[4*p4+3] = make_float4(v2.y, v2.z, v2.w, 0.5f*(v2.y*v2.y + v2.z*v2.z + v2.w*v2.w));
    }
    __syncthreads();
    int p = chunk*128 + t;
    const float* q = noisy + ((size_t)b*NN + p) * 3;
    float qx = -q[0], qy = -q[1], qz = -q[2];
    float best = INFINITY; int bidx = 0;
    #pragma unroll 8
    for (int j = 0; j < TSZ; j++) {
        float4 v = ts[j];
        float e = fmaf(qx, v.x, v.w); e = fmaf(qy, v.y, e); e = fmaf(qz, v.z, e);
        if (e < best) { best = e; bidx = j; }
    }
    int pi = b*NN + p;
    g_pbest[slice*(BB*NN) + pi] = best;
    g_pidx [slice*(BB*NN) + pi] = slice*TSZ + bidx;
}
__global__ void nn_reduce_kernel(const float* __restrict__ target)
{
    int pi = blockIdx.x * 256 + threadIdx.x;
    float best = g_pbest[pi]; int bidx = g_pidx[pi];
    #pragma unroll
    for (int s = 1; s < 4; s++) {
        float v = g_pbest[s*(BB*NN) + pi];
        if (v < best) { best = v; bidx = g_pidx[s*(BB*NN) + pi]; }
    }
    int b = pi >> 13;
    const float* tc = target + ((size_t)b*NN + bidx) * 3;
    g_nearest[pi*3+0] = tc[0]; g_nearest[pi*3+1] = tc[1]; g_nearest[pi*3+2] = tc[2];
}

// ============ fused mma.sync tf32 MLP ============
__device__ __forceinline__ void loadW(float* sm, int buf, const float* __restrict__ Wg,
                                      int kc, int nRows, int t)
{
    uint32_t base = smem_to_u32(sm + O_WB + buf*9216);
    const float* src = Wg + kc*32;
    int tot = nRows*8;
    #pragma unroll
    for (int i = t; i < tot; i += 256) {
        int n = i >> 3, j = i & 7;
        cp_async16(base + (uint32_t)((n*36 + j*4)*4), src + n*256 + j*4);
    }
}

template<int NT, bool CVT>   // NT: n8-tiles per warp (8 => N=256, 4 => N=128)
__device__ __forceinline__ void gemm_mma(float* sm, int asBase,
                                         const float* __restrict__ Wg,
                                         float c[2][NT][4],
                                         int t, int wm, int wn, int g, int tt)
{
    const int nRows = NT*8*4;
    loadW(sm, 0, Wg, 0, nRows, t); CP_COMMIT();
    #pragma unroll 1
    for (int kc = 0; kc < 8; kc++) {
        __syncthreads();                       // prior buffer consumers done
        if (kc < 7) { loadW(sm, (kc+1)&1, Wg, kc+1, nRows, t); CP_COMMIT(); cp_wait<1>(); }
        else cp_wait<0>();
        __syncthreads();                       // tile kc visible
        const uint32_t* wp = (const uint32_t*)(sm + O_WB + (kc&1)*9216);
        #pragma unroll
        for (int ks = 0; ks < 4; ks++) {
            int kb = kc*32 + ks*8;
            int u0 = kb >> 2;
            uint32_t a[2][4];
            #pragma unroll
            for (int mi = 0; mi < 2; mi++) {
                int r0 = wm*32 + mi*16 + g;
                int i00 = r0*256 + ((((u0   ) ^ g) << 2) | tt);
                int i01 = r0*256 + ((((u0+1) ^ g) << 2) | tt);
                if (CVT) {
                    a[mi][0] = tf32_bits(sm[asBase + i00]);
                    a[mi][1] = tf32_bits(sm[asBase + i00 + 2048]);
                    a[mi][2] = tf32_bits(sm[asBase + i01]);
                    a[mi][3] = tf32_bits(sm[asBase + i01 + 2048]);
                } else {
                    const uint32_t* hp = (const uint32_t*)(sm + asBase);
                    a[mi][0] = hp[i00]; a[mi][1] = hp[i00 + 2048];
                    a[mi][2] = hp[i01]; a[mi][3] = hp[i01 + 2048];
                }
            }
            uint32_t bfr[NT][2];
            #pragma unroll
            for (int nt = 0; nt < NT; nt++) {
                int n = wn*(NT*8) + nt*8 + g;
                int idx = n*36 + ks*8 + tt;
                bfr[nt][0] = wp[idx]; bfr[nt][1] = wp[idx+4];
            }
            #pragma unroll
            for (int mi = 0; mi < 2; mi++)
                #pragma unroll
                for (int nt = 0; nt < NT; nt++) mma8(c[mi][nt], a[mi], bfr[nt]);
        }
    }
    __syncthreads();
}

__global__ __launch_bounds__(256, 1)
void mlp_mma(const float* __restrict__ noisy,
             const float* __restrict__ in_w,  const float* __restrict__ in_b,
             const float* __restrict__ ly_b1, const float* __restrict__ ly_g,
             const float* __restrict__ ly_be, const float* __restrict__ ly_b2,
             const float* __restrict__ out_b1, const float* __restrict__ out_w2,
             const float* __restrict__ out_b2, float* __restrict__ out)
{
    extern __shared__ float sm[];
    int t = threadIdx.x, lane = t & 31, w = t >> 5;
    int wm = w & 1, wn = w >> 1;           // warp grid 2(M) x 4(N)
    int g = lane >> 2, tt = lane & 3;
    int b = blockIdx.x >> 7, row0 = (blockIdx.x & 127) << 6;

    // ---- stage constants ----
    if (t < 256) sm[O_CV + t] = in_b[t] + g_tproj[b*256 + t];
    for (int i = t; i < 1536; i += 256) sm[O_INW + i] = in_w[i];
    if (t < 128) sm[O_OB1 + t] = out_b1[t];
    if (t < 128) { sm[O_W2 + t] = out_w2[t]; sm[O_W2 + 128 + t] = out_w2[128 + t]; sm[O_W2 + 256 + t] = out_w2[256 + t]; }
    if (t < 3)   sm[O_OB2 + t] = out_b2[t];
    __syncthreads();

    // ---- input build: x = feat @ in_w + (in_b + tproj) ----
    {
        int row = t >> 2, q = t & 3;
        int gp = b*NN + row0 + row;
        float f[6];
        f[0]=noisy[gp*3]; f[1]=noisy[gp*3+1]; f[2]=noisy[gp*3+2];
        f[3]=g_nearest[gp*3]; f[4]=g_nearest[gp*3+1]; f[5]=g_nearest[gp*3+2];
        #pragma unroll
        for (int c4 = 0; c4 < 16; c4++) {
            int col = q*64 + c4*4;
            float4 a = *(const float4*)(sm + O_CV + col);
            #pragma unroll
            for (int k = 0; k < 6; k++) {
                float4 wv = *(const float4*)(sm + O_INW + k*256 + col);
                a.x = fmaf(f[k], wv.x, a.x); a.y = fmaf(f[k], wv.y, a.y);
                a.z = fmaf(f[k], wv.z, a.z); a.w = fmaf(f[k], wv.w, a.w);
            }
            *(float4*)(sm + O_XS + xidx(row, col)) = a;
        }
    }
    __syncthreads();

    // ---- 4 residual layers ----
    #pragma unroll 1
    for (int lay = 0; lay < 4; lay++) {
        if (t < 256) {
            sm[O_B1 + t] = ly_b1[lay*256 + t]; sm[O_GA + t] = ly_g [lay*256 + t];
            sm[O_BE + t] = ly_be[lay*256 + t]; sm[O_B2 + t] = ly_b2[lay*256 + t];
        }
        __syncthreads();

        // GEMM1: D = x @ W1   (A = xs fp32, cvt at load)
        float c1[2][8][4];
        #pragma unroll
        for (int mi = 0; mi < 2; mi++)
            #pragma unroll
            for (int nt = 0; nt < 8; nt++)
                { c1[mi][nt][0]=0.f; c1[mi][nt][1]=0.f; c1[mi][nt][2]=0.f; c1[mi][nt][3]=0.f; }
        gemm_mma<8, true>(sm, O_XS, g_wt1 + lay*65536, c1, t, wm, wn, g, tt);

        // epilogue1: +b1, LayerNorm stats, LN+SiLU -> hs (tf32)
        float S[2][2] = {{0,0},{0,0}}, Q[2][2] = {{0,0},{0,0}};
        #pragma unroll
        for (int mi = 0; mi < 2; mi++)
            #pragma unroll
            for (int nt = 0; nt < 8; nt++) {
                int bc = wn*64 + nt*8 + 2*tt;
                float b0 = sm[O_B1 + bc], b1v = sm[O_B1 + bc + 1];
                float v0 = c1[mi][nt][0] + b0, v1 = c1[mi][nt][1] + b1v;
                float v2 = c1[mi][nt][2] + b0, v3 = c1[mi][nt][3] + b1v;
                c1[mi][nt][0]=v0; c1[mi][nt][1]=v1; c1[mi][nt][2]=v2; c1[mi][nt][3]=v3;
                S[mi][0] += v0 + v1; Q[mi][0] = fmaf(v0,v0,fmaf(v1,v1,Q[mi][0]));
                S[mi][1] += v2 + v3; Q[mi][1] = fmaf(v2,v2,fmaf(v3,v3,Q[mi][1]));
            }
        #pragma unroll
        for (int mi = 0; mi < 2; mi++)
            #pragma unroll
            for (int h = 0; h < 2; h++) {
                int row = wm*32 + mi*16 + h*8 + g;
                sm[O_SRS + row*16 + wn*4 + tt] = S[mi][h];
                sm[O_SRQ + row*16 + wn*4 + tt] = Q[mi][h];
            }
        __syncthreads();
        if (t < 64) {
            float s = 0.f, q = 0.f;
            #pragma unroll
            for (int i = 0; i < 16; i++) { s += sm[O_SRS + t*16 + i]; q += sm[O_SRQ + t*16 + i]; }
            float mu = s * (1.f/256.f);
            float rs = rsqrtf(fmaf(-mu, mu, q * (1.f/256.f)) + 1e-5f);
            sm[O_MU + t] = mu; sm[O_RS + t] = rs;
        }
        __syncthreads();
        #pragma unroll
        for (int mi = 0; mi < 2; mi++)
            #pragma unroll
            for (int h = 0; h < 2; h++) {
                int row = wm*32 + mi*16 + h*8 + g;
                float mu = sm[O_MU + row], rs = sm[O_RS + row];
                #pragma unroll
                for (int nt = 0; nt < 8; nt++) {
                    int bc = wn*64 + nt*8 + 2*tt;
                    float v0 = c1[mi][nt][2*h], v1 = c1[mi][nt][2*h + 1];
                    float h0 = fmaf((v0 - mu)*rs, sm[O_GA + bc],     sm[O_BE + bc]);
                    float h1 = fmaf((v1 - mu)*rs, sm[O_GA + bc + 1], sm[O_BE + bc + 1]);
                    float2 pr;
                    pr.x = __uint_as_float(tf32_bits(silu(h0)));
                    pr.y = __uint_as_float(tf32_bits(silu(h1)));
                    *(float2*)(sm + O_HS + xidx(row, bc)) = pr;
                }
            }
        __syncthreads();

        // GEMM2: D = h @ W2  (A = hs, already tf32)
        float c2[2][8][4];
        #pragma unroll
        for (int mi = 0; mi < 2; mi++)
            #pragma unroll
            for (int nt = 0; nt < 8; nt++)
                { c2[mi][nt][0]=0.f; c2[mi][nt][1]=0.f; c2[mi][nt][2]=0.f; c2[mi][nt][3]=0.f; }
        gemm_mma<8, false>(sm, O_HS, g_wt2 + lay*65536, c2, t, wm, wn, g, tt);

        // epilogue2: x += D + b2
        #pragma unroll
        for (int mi = 0; mi < 2; mi++)
            #pragma unroll
            for (int h = 0; h < 2; h++) {
                int row = wm*32 + mi*16 + h*8 + g;
                #pragma unroll
                for (int nt = 0; nt < 8; nt++) {
                    int bc = wn*64 + nt*8 + 2*tt;
                    float2* px = (float2*)(sm + O_XS + xidx(row, bc));
                    float2 xv = *px;
                    xv.x += c2[mi][nt][2*h]     + sm[O_B2 + bc];
                    xv.y += c2[mi][nt][2*h + 1] + sm[O_B2 + bc + 1];
                    *px = xv;
                }
            }
        __syncthreads();
    }

    // ---- head GEMM: D = x @ out_w1 (N=128) ----
    float ch[2][4][4];
    #pragma unroll
    for (int mi = 0; mi < 2; mi++)
        #pragma unroll
        for (int nt = 0; nt < 4; nt++)
            { ch[mi][nt][0]=0.f; ch[mi][nt][1]=0.f; ch[mi][nt][2]=0.f; ch[mi][nt][3]=0.f; }
    gemm_mma<4, true>(sm, O_XS, g_owt1, ch, t, wm, wn, g, tt);

    // y1 = silu(D + b1) -> plain smem [64][132] (reuse HS region)
    #pragma unroll
    for (int mi = 0; mi < 2; mi++)
        #pragma unroll
        for (int h = 0; h < 2; h++) {
            int row = wm*32 + mi*16 + h*8 + g;
            #pragma unroll
            for (int nt = 0; nt < 4; nt++) {
                int bc = wn*32 + nt*8 + 2*tt;
                sm[O_HS + row*132 + bc]     = silu(ch[mi][nt][2*h]     + sm[O_OB1 + bc]);
                sm[O_HS + row*132 + bc + 1] = silu(ch[mi][nt][2*h + 1] + sm[O_OB1 + bc + 1]);
            }
        }
    __syncthreads();

    // ---- final: score = y1 @ out_w2 + out_b2 (128 -> 3) ----
    if (t < 192) {
        int rr = t / 3, p = t - rr*3;
        float a = sm[O_OB2 + p];
        const float* y = sm + O_HS + rr*132;
        #pragma unroll 8
        for (int k = 0; k < 128; k++) a = fmaf(y[k], sm[O_W2 + k*3 + p], a);
        out[(size_t)((b*NN + row0 + rr)*3 + p)] = a;
    }
}

// =====================================================================
extern "C" void kernel_launch(void* const* d_in, const int* in_sizes, int n_in,
                              void* d_out, int out_size)
{
    const float* noisy  = (const float*)d_in[0];
    const float* target = (const float*)d_in[1];
    const int*   tsteps = (const int*)  d_in[2];
    const float* te_w1  = (const float*)d_in[3];
    const float* te_b1  = (const float*)d_in[4];
    const float* te_w2  = (const float*)d_in[5];
    const float* te_b2  = (const float*)d_in[6];
    const float* tp_w   = (const float*)d_in[7];
    const float* tp_b   = (const float*)d_in[8];
    const float* in_w   = (const float*)d_in[9];
    const float* in_b   = (const float*)d_in[10];
    const float* ly_w1  = (const float*)d_in[11];
    const float* ly_b1  = (const float*)d_in[12];
    const float* ly_g   = (const float*)d_in[13];
    const float* ly_be  = (const float*)d_in[14];
    const float* ly_w2  = (const float*)d_in[15];
    const float* ly_b2  = (const float*)d_in[16];
    const float* out_w1 = (const float*)d_in[17];
    const float* out_b1 = (const float*)d_in[18];
    const float* out_w2 = (const float*)d_in[19];
    const float* out_b2 = (const float*)d_in[20];
    float* out = (float*)d_out;

    cudaFuncSetAttribute(mlp_mma, cudaFuncAttributeMaxDynamicSharedMemorySize, SMEM_BYTES);

    transpose_kernel<<<576, 256>>>(ly_w1, ly_w2, out_w1);
    temb_kernel<<<4, 512>>>(tsteps, te_w1, te_b1, te_w2, te_b2, tp_w, tp_b);
    nn_kernel<<<1024, 128>>>(noisy, target);
    nn_reduce_kernel<<<128, 256>>>(target);
    mlp_mma<<<512, 256, SMEM_BYTES>>>(noisy, in_w, in_b,
                                      ly_b1, ly_g, ly_be, ly_b2,
                                      out_b1, out_w2, out_b2, out);
}